// round 9
// baseline (speedup 1.0000x reference)
#include <cuda_runtime.h>
#include <math.h>

#define NB 4
#define CIN 1024
#define CMID 512
#define NPIX 4096
#define MTOT (NB*NPIX)      /* 16384 */
#define KTOT 9216
#define NANCH 36864
#define PRE_TOPN 6000
#define POST_TOPN 300
#define SEL_CAP 16384
#define NBUCKET 65536
#define NEGF (-1.0e10f)

static __device__ float g_wt[KTOT*CMID];
static __device__ float g_feat[(size_t)MTOT*CMID];
static __device__ float g_boxes[NB*NANCH*4];
static __device__ unsigned g_sbits[NB*NANCH];
static __device__ int g_hist[NB*NBUCKET];
static __device__ int g_thr[NB];
static __device__ int g_cnt[NB];
static __device__ unsigned long long g_sel[NB*SEL_CAP];

// base anchor widths/heights for (ratio 0.5,1,2) x (scale 8,16,32), centers all at 7.5
__constant__ float c_wa[9] = {184.f,368.f,736.f,128.f,256.f,512.f, 88.f,176.f,352.f};
__constant__ float c_ha[9] = { 96.f,192.f,384.f,128.f,256.f,512.f,176.f,352.f,704.f};

// ---- packed f32x2 helpers (Blackwell) --------------------------------------
__device__ __forceinline__ unsigned long long pk2(float x, float y){
    unsigned long long r;
    asm("mov.b64 %0, {%1,%2};" : "=l"(r) : "f"(x), "f"(y));
    return r;
}
__device__ __forceinline__ void upk2(unsigned long long v, float& x, float& y){
    asm("mov.b64 {%0,%1}, %2;" : "=f"(x), "=f"(y) : "l"(v));
}
__device__ __forceinline__ void fma2(unsigned long long& d, unsigned long long a, unsigned long long b){
    asm("fma.rn.f32x2 %0, %1, %2, %0;" : "+l"(d) : "l"(a), "l"(b));
}

// ---------------------------------------------------------------------------
// Weight transpose (coalesced, smem-tiled):
// OIHW conv_w[n][c*9+r] -> g_wt[(r*1024+c)*512 + n]
// ---------------------------------------------------------------------------
__global__ void __launch_bounds__(256)
transpose_w_kernel(const float* __restrict__ w){
    __shared__ float s[128][73];
    const int tid = threadIdx.x;
    const int n0 = blockIdx.y * 128;
    const int c0 = blockIdx.x * 8;
    const int n  = tid >> 1;
    const int half = tid & 1;
    const float* src = w + (size_t)(n0+n)*KTOT + c0*9 + half*36;
#pragma unroll
    for (int i=0;i<36;i++) s[n][half*36 + i] = src[i];
    __syncthreads();
    const int nn = tid & 127;
    const int u  = tid >> 7;
#pragma unroll
    for (int si=0; si<36; ++si){
        int slot = u*36 + si;
        int cc = slot / 9, r = slot - cc*9;
        g_wt[(size_t)(r*1024 + c0 + cc)*512 + n0 + nn] = s[nn][slot];
    }
}

__global__ void init_kernel(){
    int i = blockIdx.x*256 + threadIdx.x;
    if (i < NB*NBUCKET) g_hist[i] = 0;
    if (i < NB*SEL_CAP) g_sel[i] = 0ULL;
    if (i < NB)         g_cnt[i] = 0;
}

// ---------------------------------------------------------------------------
// 3x3 conv + bias + relu as implicit GEMM (fp32, packed f32x2 FMA).
// Tile 64(M) x 128(N), 512 threads, OCC 1 (forced via dummy dynamic smem):
// 1024 equal tiles over 148 SM slots -> 6.92 tiles/slot, makespan 7 tiles
// (~1% quantization loss vs 13.5% at 512 tiles / 296 slots).
// Thread tile 4x4; bit-identical arithmetic (same operands, rn, k-order).
// ---------------------------------------------------------------------------
__global__ void __launch_bounds__(512,1)
conv3x3_kernel(const float* __restrict__ X, const float* __restrict__ bias){
    __shared__ __align__(16) float As[2][8][64];
    __shared__ __align__(16) float Bs[2][8][128];
    const int tid = threadIdx.x;
    const int n0 = blockIdx.x * 128;
    const int m0 = blockIdx.y * 64;

    // A loader: 1 float/thread/stage; a_m consecutive -> coalesced pixels
    const int a_m = tid & 63;
    const int a_k = tid >> 6;          // 0..7
    const int am  = m0 + a_m;
    const int bb  = am >> 12;
    const int yx  = am & 4095;
    const int py  = yx >> 6;
    const int px  = yx & 63;
    const float* Xb = X + (size_t)bb * (CIN*NPIX);

    // B loader: 2 floats/thread/stage
    const int w_n  = tid & 127;
    const int w_k2 = (tid >> 7) << 1;  // 0,2,4,6

    // compute micro-tile: 4 rows x 4 cols
    const int tm = (tid >> 5) << 2;    // 0..60 (16 groups x 4 rows = 64)
    const int tn = (tid & 31) << 2;    // 0..124 (32 groups x 4 cols = 128)

    // acc2[i][jh] = packed pair (col tn+2jh, tn+2jh+1) for row tm+i
    unsigned long long acc2[4][2];
#pragma unroll
    for (int i=0;i<4;i++){ acc2[i][0]=0ULL; acc2[i][1]=0ULL; }

    float ar, br[2];
    { // prologue, ktile 0: r=0 -> (ky,kx)=(-1,-1)
        const int oy = py - 1, ox = px - 1;
        const bool ok = ((unsigned)oy < 64u) && ((unsigned)ox < 64u);
        ar = ok ? Xb[(a_k)*4096 + oy*64 + ox] : 0.f;
        const float* wp = g_wt + (size_t)w_k2*512 + n0 + w_n;
        br[0] = wp[0]; br[1] = wp[512];
        As[0][a_k][a_m] = ar;
        Bs[0][w_k2][w_n]   = br[0];
        Bs[0][w_k2+1][w_n] = br[1];
    }
    __syncthreads();

    int buf = 0;
    const int NKT = KTOT/8;   // 1152
    for (int kt = 0; kt < NKT; ++kt) {
        if (kt + 1 < NKT) {
            const int kb = (kt+1) << 3;
            const int r  = kb >> 10;          // 0..8
            const int cb = kb & 1023;
            const int ky = r/3, kx = r - ky*3;
            const int oy = py + ky - 1, ox = px + kx - 1;
            const bool ok = ((unsigned)oy < 64u) && ((unsigned)ox < 64u);
            ar = ok ? Xb[(cb + a_k)*4096 + oy*64 + ox] : 0.f;
            const float* wp = g_wt + (size_t)(kb + w_k2)*512 + n0 + w_n;
            br[0] = wp[0]; br[1] = wp[512];
        }
#pragma unroll
        for (int kk=0;kk<8;kk++){
            float4 t0 = *(const float4*)&As[buf][kk][tm];
            unsigned long long a2[4];
            a2[0]=pk2(t0.x,t0.x); a2[1]=pk2(t0.y,t0.y);
            a2[2]=pk2(t0.z,t0.z); a2[3]=pk2(t0.w,t0.w);
            unsigned long long b2[2];
            {
                const unsigned long long* q = (const unsigned long long*)&Bs[buf][kk][tn];
                b2[0]=q[0]; b2[1]=q[1];
            }
#pragma unroll
            for (int jh=0;jh<2;jh++)
#pragma unroll
                for (int i=0;i<4;i++)
                    fma2(acc2[i][jh], a2[i], b2[jh]);
        }
        if (kt + 1 < NKT) {
            const int nb2 = buf^1;
            As[nb2][a_k][a_m] = ar;
            Bs[nb2][w_k2][w_n]   = br[0];
            Bs[nb2][w_k2+1][w_n] = br[1];
        }
        __syncthreads();
        buf ^= 1;
    }

    // epilogue: bias + relu -> g_feat
    const float b0 = bias[n0+tn+0], b1 = bias[n0+tn+1];
    const float b2v = bias[n0+tn+2], b3 = bias[n0+tn+3];
#pragma unroll
    for (int i=0;i<4;i++){
        const int mr = m0 + tm + i;
        float v0,v1,v2,v3;
        upk2(acc2[i][0], v0, v1);
        upk2(acc2[i][1], v2, v3);
        float4 o;
        o.x = fmaxf(v0 + b0, 0.f);
        o.y = fmaxf(v1 + b1, 0.f);
        o.z = fmaxf(v2 + b2v, 0.f);
        o.w = fmaxf(v3 + b3, 0.f);
        *(float4*)(g_feat + (size_t)mr*CMID + n0 + tn) = o;
    }
}

// ---------------------------------------------------------------------------
// 1x1 heads + softmax + anchor decode + clip + histogram (4 px per warp-iter).
// ---------------------------------------------------------------------------
__global__ void __launch_bounds__(512)
head_kernel(const float* __restrict__ cls_w, const float* __restrict__ cls_b,
            const float* __restrict__ bbox_w, const float* __restrict__ bbox_b,
            const float* __restrict__ im_info){
    extern __shared__ float ws[];
    __shared__ float bs[54];
    __shared__ float obuf[16][4][54];
    const int tid = threadIdx.x;
    for (int i = tid; i < 18*512; i += 512) ws[i] = cls_w[i];
    for (int i = tid; i < 36*512; i += 512) ws[18*512 + i] = bbox_w[i];
    if (tid < 18) bs[tid] = cls_b[tid];
    else if (tid < 54) bs[tid] = bbox_b[tid-18];
    __syncthreads();

    const int lane = tid & 31;
    const int warp = tid >> 5;
    const int gw = blockIdx.x*16 + warp;
    const int nw = gridDim.x*16;
    for (int mb = gw*4; mb < MTOT; mb += nw*4) {
        float fr[4][16];
#pragma unroll
        for (int p=0;p<4;p++){
            const float* f = g_feat + (size_t)(mb+p)*CMID;
#pragma unroll
            for (int j=0;j<16;j++) fr[p][j] = f[lane + 32*j];
        }
        for (int t=0;t<54;t++){
            const float* wr = ws + t*512;
            float s0=0.f, s1=0.f, s2=0.f, s3=0.f;
#pragma unroll
            for (int j=0;j<16;j++){
                float wv = wr[lane+32*j];
                s0 += fr[0][j]*wv; s1 += fr[1][j]*wv;
                s2 += fr[2][j]*wv; s3 += fr[3][j]*wv;
            }
#pragma unroll
            for (int d=16; d>0; d>>=1){
                s0 += __shfl_xor_sync(0xffffffffu, s0, d);
                s1 += __shfl_xor_sync(0xffffffffu, s1, d);
                s2 += __shfl_xor_sync(0xffffffffu, s2, d);
                s3 += __shfl_xor_sync(0xffffffffu, s3, d);
            }
            if (lane==0){
                float bv = bs[t];
                obuf[warp][0][t] = s0 + bv;
                obuf[warp][1][t] = s1 + bv;
                obuf[warp][2][t] = s2 + bv;
                obuf[warp][3][t] = s3 + bv;
            }
        }
        __syncwarp();
#pragma unroll
        for (int p=0;p<4;p++){
            if (lane < 9) {
                const float* o = obuf[warp][p];
                const int m = mb + p;
                const int a  = lane;
                const int b  = m >> 12;
                const int yx = m & 4095;
                const int py = yx >> 6, px = yx & 63;
                float c0 = o[a], c1 = o[9+a];
                float mx = fmaxf(c0,c1);
                float e0 = expf(c0-mx), e1 = expf(c1-mx);
                float sc = e1/(e0+e1);
                float dx = o[18+a*4+0], dy = o[18+a*4+1];
                float dw = o[18+a*4+2], dh = o[18+a*4+3];
                float wa = c_wa[a], ha = c_ha[a];
                float cxa = 7.5f + 16.f*(float)px;
                float cya = 7.5f + 16.f*(float)py;
                float cx = dx*wa + cxa;
                float cy = dy*ha + cya;
                float pw = expf(dw)*wa;
                float ph = expf(dh)*ha;
                float imh = im_info[b*3+0], imw = im_info[b*3+1];
                float x1 = fminf(fmaxf(cx - 0.5f*pw, 0.f), imw - 1.f);
                float y1 = fminf(fmaxf(cy - 0.5f*ph, 0.f), imh - 1.f);
                float x2 = fminf(fmaxf(cx + 0.5f*pw, 0.f), imw - 1.f);
                float y2 = fminf(fmaxf(cy + 0.5f*ph, 0.f), imh - 1.f);
                const int idx = yx*9 + a;
                float* bp = g_boxes + ((size_t)b*NANCH + idx)*4;
                bp[0]=x1; bp[1]=y1; bp[2]=x2; bp[3]=y2;
                unsigned bits = __float_as_uint(sc);
                g_sbits[b*NANCH + idx] = bits;
                atomicAdd(&g_hist[b*NBUCKET + (bits>>16)], 1);
            }
        }
        __syncwarp();
    }
}

// ---------------------------------------------------------------------------
__global__ void __launch_bounds__(1024) thresh_kernel(){
    __shared__ int csum[1024];
    const int b = blockIdx.x;
    const int t = threadIdx.x;
    const int* h = g_hist + b*NBUCKET;
    const int base = t*64;
    int s = 0;
    for (int i=0;i<64;i++) s += h[base+i];
    csum[t] = s;
    __syncthreads();
    for (int d=1; d<1024; d<<=1){
        int add = (t+d < 1024) ? csum[t+d] : 0;
        __syncthreads();
        csum[t] += add;
        __syncthreads();
    }
    int St = csum[t];
    int Sn = (t+1 < 1024) ? csum[t+1] : 0;
    if (St >= PRE_TOPN && Sn < PRE_TOPN){
        int acc = Sn;
        int T = base;
        for (int i=63;i>=0;i--){
            acc += h[base+i];
            if (acc >= PRE_TOPN){ T = base+i; break; }
        }
        g_thr[b] = T;
    }
}

__global__ void compact_kernel(){
    int i = blockIdx.x*256 + threadIdx.x;
    if (i >= NB*NANCH) return;
    int b = i / NANCH;
    int idx = i - b*NANCH;
    unsigned bits = g_sbits[i];
    if ((int)(bits >> 16) >= g_thr[b]){
        int p = atomicAdd(&g_cnt[b], 1);
        if (p < SEL_CAP)
            g_sel[b*SEL_CAP + p] = ((unsigned long long)bits << 32) | (unsigned)(~idx);
    }
}

__global__ void __launch_bounds__(1024) sort_kernel(){
    extern __shared__ unsigned long long sh[];
    const int b = blockIdx.x;
    unsigned long long* gs = g_sel + b*SEL_CAP;
    for (int i=threadIdx.x;i<SEL_CAP;i+=1024) sh[i] = gs[i];
    __syncthreads();
    for (int k=2;k<=SEL_CAP;k<<=1){
        for (int j=k>>1;j>0;j>>=1){
            for (int t=threadIdx.x;t<SEL_CAP/2;t+=1024){
                int i  = 2*t - (t & (j-1));
                int ix = i + j;
                unsigned long long a = sh[i], c = sh[ix];
                bool dir = ((i & k) == 0);
                bool sw  = dir ? (a < c) : (a > c);
                if (sw){ sh[i]=c; sh[ix]=a; }
            }
            __syncthreads();
        }
    }
    for (int i=threadIdx.x;i<SEL_CAP;i+=1024) gs[i]=sh[i];
}

__global__ void __launch_bounds__(1024) nms_kernel(float* __restrict__ out){
    extern __shared__ float sm[];
    float* X1 = sm;
    float* Y1 = X1 + PRE_TOPN;
    float* X2 = Y1 + PRE_TOPN;
    float* Y2 = X2 + PRE_TOPN;
    float* AR = Y2 + PRE_TOPN;
    float* SC = AR + PRE_TOPN;
    __shared__ int   s_pick;
    __shared__ float s_box[5];
    const int b = blockIdx.x;
    const unsigned long long* keys = g_sel + b*SEL_CAP;
    for (int i=threadIdx.x;i<PRE_TOPN;i+=1024){
        unsigned long long kv = keys[i];
        unsigned idx = ~(unsigned)(kv & 0xFFFFFFFFull);
        float sc = __uint_as_float((unsigned)(kv >> 32));
        const float* bp = g_boxes + ((size_t)b*NANCH + idx)*4;
        float x1=bp[0], y1=bp[1], x2=bp[2], y2=bp[3];
        X1[i]=x1; Y1[i]=y1; X2[i]=x2; Y2[i]=y2;
        AR[i]=(x2-x1+1.f)*(y2-y1+1.f);
        SC[i]=sc;
    }
    __syncthreads();
    int p = 0;
    for (int it=0; it<POST_TOPN; ++it){
        if (threadIdx.x == 0){
            while (p < PRE_TOPN && SC[p] == NEGF) p++;
            if (p < PRE_TOPN){
                s_pick = p;
                s_box[0]=X1[p]; s_box[1]=Y1[p]; s_box[2]=X2[p]; s_box[3]=Y2[p]; s_box[4]=AR[p];
                float* r = out + (size_t)(b*POST_TOPN + it)*5;
                r[0]=(float)b; r[1]=X1[p]; r[2]=Y1[p]; r[3]=X2[p]; r[4]=Y2[p];
                out[NB*POST_TOPN*5 + b*POST_TOPN + it] = SC[p];
            } else {
                s_pick = -1;
                float* r = out + (size_t)(b*POST_TOPN + it)*5;
                r[0]=0.f; r[1]=0.f; r[2]=0.f; r[3]=0.f; r[4]=0.f;
                out[NB*POST_TOPN*5 + b*POST_TOPN + it] = 0.f;
            }
        }
        __syncthreads();
        if (s_pick >= 0){
            float bx1=s_box[0], by1=s_box[1], bx2=s_box[2], by2=s_box[3], ba=s_box[4];
            for (int i=threadIdx.x;i<PRE_TOPN;i+=1024){
                float sc = SC[i];
                if (sc == NEGF) continue;
                float xx1 = fmaxf(bx1, X1[i]);
                float yy1 = fmaxf(by1, Y1[i]);
                float xx2 = fminf(bx2, X2[i]);
                float yy2 = fminf(by2, Y2[i]);
                float iw = fmaxf(xx2-xx1+1.f, 0.f);
                float ih = fmaxf(yy2-yy1+1.f, 0.f);
                float inter = iw*ih;
                float iou = inter/(ba + AR[i] - inter);
                if (iou > 0.7f) SC[i] = NEGF;
            }
        }
        __syncthreads();
    }
}

// ---------------------------------------------------------------------------
extern "C" void kernel_launch(void* const* d_in, const int* in_sizes, int n_in,
                              void* d_out, int out_size) {
    (void)in_sizes; (void)n_in; (void)out_size;
    const float* base_feat = (const float*)d_in[0];
    const float* im_info   = (const float*)d_in[1];
    const float* conv_w    = (const float*)d_in[4];
    const float* conv_b    = (const float*)d_in[5];
    const float* cls_w     = (const float*)d_in[6];
    const float* cls_b     = (const float*)d_in[7];
    const float* bbox_w    = (const float*)d_in[8];
    const float* bbox_b    = (const float*)d_in[9];
    float* out = (float*)d_out;

    // Dummy dynamic smem (unused) forces occupancy 1 for the conv kernel:
    // 148 slots, 1024 tiles -> 6.92 tiles/slot -> ~1% wave quantization.
    cudaFuncSetAttribute(conv3x3_kernel, cudaFuncAttributeMaxDynamicSharedMemorySize, 120*1024);
    cudaFuncSetAttribute(head_kernel, cudaFuncAttributeMaxDynamicSharedMemorySize, 54*512*4);
    cudaFuncSetAttribute(sort_kernel, cudaFuncAttributeMaxDynamicSharedMemorySize, SEL_CAP*8);
    cudaFuncSetAttribute(nms_kernel,  cudaFuncAttributeMaxDynamicSharedMemorySize, PRE_TOPN*6*4);

    transpose_w_kernel<<<dim3(128,4), 256>>>(conv_w);
    init_kernel<<<(NB*NBUCKET + 255)/256, 256>>>();
    conv3x3_kernel<<<dim3(4,256), 512, 120*1024>>>(base_feat, conv_b);
    head_kernel<<<148, 512, 54*512*4>>>(cls_w, cls_b, bbox_w, bbox_b, im_info);
    thresh_kernel<<<NB, 1024>>>();
    compact_kernel<<<(NB*NANCH + 255)/256, 256>>>();
    sort_kernel<<<NB, 1024, SEL_CAP*8>>>();
    nms_kernel<<<NB, 1024, PRE_TOPN*6*4>>>(out);
}

// round 10
// speedup vs baseline: 1.1168x; 1.1168x over previous
#include <cuda_runtime.h>
#include <math.h>

#define NB 4
#define CIN 1024
#define CMID 512
#define NPIX 4096
#define MTOT (NB*NPIX)      /* 16384 */
#define KTOT 9216
#define NANCH 36864
#define PRE_TOPN 6000
#define POST_TOPN 300
#define SEL_CAP 16384
#define NBUCKET 65536
#define NEGF (-1.0e10f)

static __device__ float g_wt[KTOT*CMID];
static __device__ float g_feat[(size_t)MTOT*CMID];
static __device__ float g_boxes[NB*NANCH*4];
static __device__ unsigned g_sbits[NB*NANCH];
static __device__ int g_hist[NB*NBUCKET];
static __device__ int g_thr[NB];
static __device__ int g_cnt[NB];
static __device__ unsigned long long g_sel[NB*SEL_CAP];

// base anchor widths/heights for (ratio 0.5,1,2) x (scale 8,16,32), centers all at 7.5
__constant__ float c_wa[9] = {184.f,368.f,736.f,128.f,256.f,512.f, 88.f,176.f,352.f};
__constant__ float c_ha[9] = { 96.f,192.f,384.f,128.f,256.f,512.f,176.f,352.f,704.f};

// ---- packed f32x2 helpers (Blackwell) --------------------------------------
__device__ __forceinline__ unsigned long long pk2(float x, float y){
    unsigned long long r;
    asm("mov.b64 %0, {%1,%2};" : "=l"(r) : "f"(x), "f"(y));
    return r;
}
__device__ __forceinline__ void upk2(unsigned long long v, float& x, float& y){
    asm("mov.b64 {%0,%1}, %2;" : "=f"(x), "=f"(y) : "l"(v));
}
__device__ __forceinline__ void fma2(unsigned long long& d, unsigned long long a, unsigned long long b){
    asm("fma.rn.f32x2 %0, %1, %2, %0;" : "+l"(d) : "l"(a), "l"(b));
}

// ---------------------------------------------------------------------------
// Weight transpose (coalesced, smem-tiled):
// OIHW conv_w[n][c*9+r] -> g_wt[(r*1024+c)*512 + n]
// ---------------------------------------------------------------------------
__global__ void __launch_bounds__(256)
transpose_w_kernel(const float* __restrict__ w){
    __shared__ float s[128][73];
    const int tid = threadIdx.x;
    const int n0 = blockIdx.y * 128;
    const int c0 = blockIdx.x * 8;
    const int n  = tid >> 1;
    const int half = tid & 1;
    const float* src = w + (size_t)(n0+n)*KTOT + c0*9 + half*36;
#pragma unroll
    for (int i=0;i<36;i++) s[n][half*36 + i] = src[i];
    __syncthreads();
    const int nn = tid & 127;
    const int u  = tid >> 7;
#pragma unroll
    for (int si=0; si<36; ++si){
        int slot = u*36 + si;
        int cc = slot / 9, r = slot - cc*9;
        g_wt[(size_t)(r*1024 + c0 + cc)*512 + n0 + nn] = s[nn][slot];
    }
}

__global__ void init_kernel(){
    int i = blockIdx.x*256 + threadIdx.x;
    if (i < NB*NBUCKET) g_hist[i] = 0;
    if (i < NB*SEL_CAP) g_sel[i] = 0ULL;
    if (i < NB)         g_cnt[i] = 0;
}

// ---------------------------------------------------------------------------
// 3x3 conv + bias + relu as implicit GEMM (fp32, packed f32x2 FMA).
// Tile 64(M) x 128(N), 256 threads, occ 2 (R6 recipe: same warps/SMSP, same
// issue mix, co-resident CTA hides sync drains). 1024 tiles -> 6.92 tiles/SM
// -> makespan 7 (1.2% quantization vs 15.6% at 512 tiles).
// Thread tile 4x8; bit-identical per-output k-chains to the scalar baseline.
// ---------------------------------------------------------------------------
__global__ void __launch_bounds__(256,2)
conv3x3_kernel(const float* __restrict__ X, const float* __restrict__ bias){
    __shared__ __align__(16) float As[2][8][64];
    __shared__ __align__(16) float Bs[2][8][128];
    const int tid = threadIdx.x;
    const int n0 = blockIdx.x * 128;
    const int m0 = blockIdx.y * 64;

    // A loader: 2 floats/thread/stage (k = a_k, a_k+4 for pixel a_m)
    const int a_m = tid & 63;
    const int a_k = tid >> 6;          // 0..3
    const int am  = m0 + a_m;
    const int bb  = am >> 12;
    const int yx  = am & 4095;
    const int py  = yx >> 6;
    const int px  = yx & 63;
    const float* Xb = X + (size_t)bb * (CIN*NPIX);

    // B loader: 4 floats/thread/stage
    const int w_n  = tid & 127;
    const int w_k4 = (tid >> 7) << 2;  // 0 or 4

    // compute micro-tile: 4 rows x 8 cols (contiguous)
    const int tm = (tid >> 4) << 2;    // 0..60
    const int tn = (tid & 15) << 3;    // 0..120

    // acc2[i][jh] = packed pair (col tn+2jh, tn+2jh+1) for row tm+i
    unsigned long long acc2[4][4];
#pragma unroll
    for (int i=0;i<4;i++)
#pragma unroll
        for (int jh=0;jh<4;jh++) acc2[i][jh] = 0ULL;

    float ar[2], br[4];
    { // prologue, ktile 0: r=0 -> (ky,kx)=(-1,-1)
        const int oy = py - 1, ox = px - 1;
        const bool ok = ((unsigned)oy < 64u) && ((unsigned)ox < 64u);
        const float* ap = Xb + (a_k*4096 + oy*64 + ox);
        ar[0] = ok ? ap[0] : 0.f;
        ar[1] = ok ? ap[4*4096] : 0.f;
        const float* wp = g_wt + (size_t)w_k4*512 + n0 + w_n;
#pragma unroll
        for (int i=0;i<4;i++) br[i] = wp[i*512];
        As[0][a_k][a_m]   = ar[0];
        As[0][a_k+4][a_m] = ar[1];
#pragma unroll
        for (int i=0;i<4;i++) Bs[0][w_k4+i][w_n] = br[i];
    }
    __syncthreads();

    int buf = 0;
    const int NKT = KTOT/8;   // 1152
    for (int kt = 0; kt < NKT; ++kt) {
        if (kt + 1 < NKT) {
            const int kb = (kt+1) << 3;
            const int r  = kb >> 10;          // 0..8
            const int cb = kb & 1023;
            const int ky = r/3, kx = r - ky*3;
            const int oy = py + ky - 1, ox = px + kx - 1;
            const bool ok = ((unsigned)oy < 64u) && ((unsigned)ox < 64u);
            const float* ap = Xb + ((cb + a_k)*4096 + oy*64 + ox);
            ar[0] = ok ? ap[0] : 0.f;
            ar[1] = ok ? ap[4*4096] : 0.f;
            const float* wp = g_wt + (size_t)(kb + w_k4)*512 + n0 + w_n;
#pragma unroll
            for (int i=0;i<4;i++) br[i] = wp[i*512];
        }
#pragma unroll
        for (int kk=0;kk<8;kk++){
            float4 t0 = *(const float4*)&As[buf][kk][tm];
            unsigned long long a2[4];
            a2[0]=pk2(t0.x,t0.x); a2[1]=pk2(t0.y,t0.y);
            a2[2]=pk2(t0.z,t0.z); a2[3]=pk2(t0.w,t0.w);
            unsigned long long b2[4];
            {
                const unsigned long long* q = (const unsigned long long*)&Bs[buf][kk][tn];
                b2[0]=q[0]; b2[1]=q[1]; b2[2]=q[2]; b2[3]=q[3];
            }
#pragma unroll
            for (int jh=0;jh<4;jh++)
#pragma unroll
                for (int i=0;i<4;i++)
                    fma2(acc2[i][jh], a2[i], b2[jh]);
        }
        if (kt + 1 < NKT) {
            const int nb2 = buf^1;
            As[nb2][a_k][a_m]   = ar[0];
            As[nb2][a_k+4][a_m] = ar[1];
#pragma unroll
            for (int i=0;i<4;i++) Bs[nb2][w_k4+i][w_n] = br[i];
        }
        __syncthreads();
        buf ^= 1;
    }

    // epilogue: bias + relu -> g_feat (8 contiguous cols per thread)
    float bv[8];
#pragma unroll
    for (int j=0;j<8;j++) bv[j] = bias[n0+tn+j];
#pragma unroll
    for (int i=0;i<4;i++){
        const int mr = m0 + tm + i;
        float v[8];
#pragma unroll
        for (int jh=0;jh<4;jh++) upk2(acc2[i][jh], v[2*jh], v[2*jh+1]);
        float4 o0, o1;
        o0.x = fmaxf(v[0]+bv[0], 0.f); o0.y = fmaxf(v[1]+bv[1], 0.f);
        o0.z = fmaxf(v[2]+bv[2], 0.f); o0.w = fmaxf(v[3]+bv[3], 0.f);
        o1.x = fmaxf(v[4]+bv[4], 0.f); o1.y = fmaxf(v[5]+bv[5], 0.f);
        o1.z = fmaxf(v[6]+bv[6], 0.f); o1.w = fmaxf(v[7]+bv[7], 0.f);
        float* op = g_feat + (size_t)mr*CMID + n0 + tn;
        *(float4*)op = o0;
        *(float4*)(op+4) = o1;
    }
}

// ---------------------------------------------------------------------------
// 1x1 heads + softmax + anchor decode + clip + histogram (4 px per warp-iter).
// ---------------------------------------------------------------------------
__global__ void __launch_bounds__(512)
head_kernel(const float* __restrict__ cls_w, const float* __restrict__ cls_b,
            const float* __restrict__ bbox_w, const float* __restrict__ bbox_b,
            const float* __restrict__ im_info){
    extern __shared__ float ws[];
    __shared__ float bs[54];
    __shared__ float obuf[16][4][54];
    const int tid = threadIdx.x;
    for (int i = tid; i < 18*512; i += 512) ws[i] = cls_w[i];
    for (int i = tid; i < 36*512; i += 512) ws[18*512 + i] = bbox_w[i];
    if (tid < 18) bs[tid] = cls_b[tid];
    else if (tid < 54) bs[tid] = bbox_b[tid-18];
    __syncthreads();

    const int lane = tid & 31;
    const int warp = tid >> 5;
    const int gw = blockIdx.x*16 + warp;
    const int nw = gridDim.x*16;
    for (int mb = gw*4; mb < MTOT; mb += nw*4) {
        float fr[4][16];
#pragma unroll
        for (int p=0;p<4;p++){
            const float* f = g_feat + (size_t)(mb+p)*CMID;
#pragma unroll
            for (int j=0;j<16;j++) fr[p][j] = f[lane + 32*j];
        }
        for (int t=0;t<54;t++){
            const float* wr = ws + t*512;
            float s0=0.f, s1=0.f, s2=0.f, s3=0.f;
#pragma unroll
            for (int j=0;j<16;j++){
                float wv = wr[lane+32*j];
                s0 += fr[0][j]*wv; s1 += fr[1][j]*wv;
                s2 += fr[2][j]*wv; s3 += fr[3][j]*wv;
            }
#pragma unroll
            for (int d=16; d>0; d>>=1){
                s0 += __shfl_xor_sync(0xffffffffu, s0, d);
                s1 += __shfl_xor_sync(0xffffffffu, s1, d);
                s2 += __shfl_xor_sync(0xffffffffu, s2, d);
                s3 += __shfl_xor_sync(0xffffffffu, s3, d);
            }
            if (lane==0){
                float bv = bs[t];
                obuf[warp][0][t] = s0 + bv;
                obuf[warp][1][t] = s1 + bv;
                obuf[warp][2][t] = s2 + bv;
                obuf[warp][3][t] = s3 + bv;
            }
        }
        __syncwarp();
#pragma unroll
        for (int p=0;p<4;p++){
            if (lane < 9) {
                const float* o = obuf[warp][p];
                const int m = mb + p;
                const int a  = lane;
                const int b  = m >> 12;
                const int yx = m & 4095;
                const int py = yx >> 6, px = yx & 63;
                float c0 = o[a], c1 = o[9+a];
                float mx = fmaxf(c0,c1);
                float e0 = expf(c0-mx), e1 = expf(c1-mx);
                float sc = e1/(e0+e1);
                float dx = o[18+a*4+0], dy = o[18+a*4+1];
                float dw = o[18+a*4+2], dh = o[18+a*4+3];
                float wa = c_wa[a], ha = c_ha[a];
                float cxa = 7.5f + 16.f*(float)px;
                float cya = 7.5f + 16.f*(float)py;
                float cx = dx*wa + cxa;
                float cy = dy*ha + cya;
                float pw = expf(dw)*wa;
                float ph = expf(dh)*ha;
                float imh = im_info[b*3+0], imw = im_info[b*3+1];
                float x1 = fminf(fmaxf(cx - 0.5f*pw, 0.f), imw - 1.f);
                float y1 = fminf(fmaxf(cy - 0.5f*ph, 0.f), imh - 1.f);
                float x2 = fminf(fmaxf(cx + 0.5f*pw, 0.f), imw - 1.f);
                float y2 = fminf(fmaxf(cy + 0.5f*ph, 0.f), imh - 1.f);
                const int idx = yx*9 + a;
                float* bp = g_boxes + ((size_t)b*NANCH + idx)*4;
                bp[0]=x1; bp[1]=y1; bp[2]=x2; bp[3]=y2;
                unsigned bits = __float_as_uint(sc);
                g_sbits[b*NANCH + idx] = bits;
                atomicAdd(&g_hist[b*NBUCKET + (bits>>16)], 1);
            }
        }
        __syncwarp();
    }
}

// ---------------------------------------------------------------------------
__global__ void __launch_bounds__(1024) thresh_kernel(){
    __shared__ int csum[1024];
    const int b = blockIdx.x;
    const int t = threadIdx.x;
    const int* h = g_hist + b*NBUCKET;
    const int base = t*64;
    int s = 0;
    for (int i=0;i<64;i++) s += h[base+i];
    csum[t] = s;
    __syncthreads();
    for (int d=1; d<1024; d<<=1){
        int add = (t+d < 1024) ? csum[t+d] : 0;
        __syncthreads();
        csum[t] += add;
        __syncthreads();
    }
    int St = csum[t];
    int Sn = (t+1 < 1024) ? csum[t+1] : 0;
    if (St >= PRE_TOPN && Sn < PRE_TOPN){
        int acc = Sn;
        int T = base;
        for (int i=63;i>=0;i--){
            acc += h[base+i];
            if (acc >= PRE_TOPN){ T = base+i; break; }
        }
        g_thr[b] = T;
    }
}

__global__ void compact_kernel(){
    int i = blockIdx.x*256 + threadIdx.x;
    if (i >= NB*NANCH) return;
    int b = i / NANCH;
    int idx = i - b*NANCH;
    unsigned bits = g_sbits[i];
    if ((int)(bits >> 16) >= g_thr[b]){
        int p = atomicAdd(&g_cnt[b], 1);
        if (p < SEL_CAP)
            g_sel[b*SEL_CAP + p] = ((unsigned long long)bits << 32) | (unsigned)(~idx);
    }
}

__global__ void __launch_bounds__(1024) sort_kernel(){
    extern __shared__ unsigned long long sh[];
    const int b = blockIdx.x;
    unsigned long long* gs = g_sel + b*SEL_CAP;
    for (int i=threadIdx.x;i<SEL_CAP;i+=1024) sh[i] = gs[i];
    __syncthreads();
    for (int k=2;k<=SEL_CAP;k<<=1){
        for (int j=k>>1;j>0;j>>=1){
            for (int t=threadIdx.x;t<SEL_CAP/2;t+=1024){
                int i  = 2*t - (t & (j-1));
                int ix = i + j;
                unsigned long long a = sh[i], c = sh[ix];
                bool dir = ((i & k) == 0);
                bool sw  = dir ? (a < c) : (a > c);
                if (sw){ sh[i]=c; sh[ix]=a; }
            }
            __syncthreads();
        }
    }
    for (int i=threadIdx.x;i<SEL_CAP;i+=1024) gs[i]=sh[i];
}

__global__ void __launch_bounds__(1024) nms_kernel(float* __restrict__ out){
    extern __shared__ float sm[];
    float* X1 = sm;
    float* Y1 = X1 + PRE_TOPN;
    float* X2 = Y1 + PRE_TOPN;
    float* Y2 = X2 + PRE_TOPN;
    float* AR = Y2 + PRE_TOPN;
    float* SC = AR + PRE_TOPN;
    __shared__ int   s_pick;
    __shared__ float s_box[5];
    const int b = blockIdx.x;
    const unsigned long long* keys = g_sel + b*SEL_CAP;
    for (int i=threadIdx.x;i<PRE_TOPN;i+=1024){
        unsigned long long kv = keys[i];
        unsigned idx = ~(unsigned)(kv & 0xFFFFFFFFull);
        float sc = __uint_as_float((unsigned)(kv >> 32));
        const float* bp = g_boxes + ((size_t)b*NANCH + idx)*4;
        float x1=bp[0], y1=bp[1], x2=bp[2], y2=bp[3];
        X1[i]=x1; Y1[i]=y1; X2[i]=x2; Y2[i]=y2;
        AR[i]=(x2-x1+1.f)*(y2-y1+1.f);
        SC[i]=sc;
    }
    __syncthreads();
    int p = 0;
    for (int it=0; it<POST_TOPN; ++it){
        if (threadIdx.x == 0){
            while (p < PRE_TOPN && SC[p] == NEGF) p++;
            if (p < PRE_TOPN){
                s_pick = p;
                s_box[0]=X1[p]; s_box[1]=Y1[p]; s_box[2]=X2[p]; s_box[3]=Y2[p]; s_box[4]=AR[p];
                float* r = out + (size_t)(b*POST_TOPN + it)*5;
                r[0]=(float)b; r[1]=X1[p]; r[2]=Y1[p]; r[3]=X2[p]; r[4]=Y2[p];
                out[NB*POST_TOPN*5 + b*POST_TOPN + it] = SC[p];
            } else {
                s_pick = -1;
                float* r = out + (size_t)(b*POST_TOPN + it)*5;
                r[0]=0.f; r[1]=0.f; r[2]=0.f; r[3]=0.f; r[4]=0.f;
                out[NB*POST_TOPN*5 + b*POST_TOPN + it] = 0.f;
            }
        }
        __syncthreads();
        if (s_pick >= 0){
            float bx1=s_box[0], by1=s_box[1], bx2=s_box[2], by2=s_box[3], ba=s_box[4];
            for (int i=threadIdx.x;i<PRE_TOPN;i+=1024){
                float sc = SC[i];
                if (sc == NEGF) continue;
                float xx1 = fmaxf(bx1, X1[i]);
                float yy1 = fmaxf(by1, Y1[i]);
                float xx2 = fminf(bx2, X2[i]);
                float yy2 = fminf(by2, Y2[i]);
                float iw = fmaxf(xx2-xx1+1.f, 0.f);
                float ih = fmaxf(yy2-yy1+1.f, 0.f);
                float inter = iw*ih;
                float iou = inter/(ba + AR[i] - inter);
                if (iou > 0.7f) SC[i] = NEGF;
            }
        }
        __syncthreads();
    }
}

// ---------------------------------------------------------------------------
extern "C" void kernel_launch(void* const* d_in, const int* in_sizes, int n_in,
                              void* d_out, int out_size) {
    (void)in_sizes; (void)n_in; (void)out_size;
    const float* base_feat = (const float*)d_in[0];
    const float* im_info   = (const float*)d_in[1];
    const float* conv_w    = (const float*)d_in[4];
    const float* conv_b    = (const float*)d_in[5];
    const float* cls_w     = (const float*)d_in[6];
    const float* cls_b     = (const float*)d_in[7];
    const float* bbox_w    = (const float*)d_in[8];
    const float* bbox_b    = (const float*)d_in[9];
    float* out = (float*)d_out;

    cudaFuncSetAttribute(head_kernel, cudaFuncAttributeMaxDynamicSharedMemorySize, 54*512*4);
    cudaFuncSetAttribute(sort_kernel, cudaFuncAttributeMaxDynamicSharedMemorySize, SEL_CAP*8);
    cudaFuncSetAttribute(nms_kernel,  cudaFuncAttributeMaxDynamicSharedMemorySize, PRE_TOPN*6*4);

    transpose_w_kernel<<<dim3(128,4), 256>>>(conv_w);
    init_kernel<<<(NB*NBUCKET + 255)/256, 256>>>();
    conv3x3_kernel<<<dim3(4,256), 256>>>(base_feat, conv_b);
    head_kernel<<<148, 512, 54*512*4>>>(cls_w, cls_b, bbox_w, bbox_b, im_info);
    thresh_kernel<<<NB, 1024>>>();
    compact_kernel<<<(NB*NANCH + 255)/256, 256>>>();
    sort_kernel<<<NB, 1024, SEL_CAP*8>>>();
    nms_kernel<<<NB, 1024, PRE_TOPN*6*4>>>(out);
}

// round 11
// speedup vs baseline: 1.8707x; 1.6750x over previous
#include <cuda_runtime.h>
#include <math.h>

#define NB 4
#define CIN 1024
#define CMID 512
#define NPIX 4096
#define MTOT (NB*NPIX)      /* 16384 */
#define KTOT 9216
#define NSPLIT 4
#define KQ (KTOT/NSPLIT)    /* 2304 */
#define NANCH 36864
#define PRE_TOPN 6000
#define POST_TOPN 300
#define SEL_CAP 16384
#define NBUCKET 65536
#define NEGF (-1.0e10f)

static __device__ float g_wt[KTOT*CMID];
static __device__ float g_part[(size_t)NSPLIT*MTOT*CMID];   // split-K partials
static __device__ float g_feat[(size_t)MTOT*CMID];
static __device__ float g_boxes[NB*NANCH*4];
static __device__ unsigned g_sbits[NB*NANCH];
static __device__ int g_hist[NB*NBUCKET];
static __device__ int g_thr[NB];
static __device__ int g_cnt[NB];
static __device__ unsigned long long g_sel[NB*SEL_CAP];

// base anchor widths/heights for (ratio 0.5,1,2) x (scale 8,16,32), centers all at 7.5
__constant__ float c_wa[9] = {184.f,368.f,736.f,128.f,256.f,512.f, 88.f,176.f,352.f};
__constant__ float c_ha[9] = { 96.f,192.f,384.f,128.f,256.f,512.f,176.f,352.f,704.f};

// ---- packed f32x2 helpers (Blackwell) --------------------------------------
__device__ __forceinline__ unsigned long long pk2(float x, float y){
    unsigned long long r;
    asm("mov.b64 %0, {%1,%2};" : "=l"(r) : "f"(x), "f"(y));
    return r;
}
__device__ __forceinline__ void upk2(unsigned long long v, float& x, float& y){
    asm("mov.b64 {%0,%1}, %2;" : "=f"(x), "=f"(y) : "l"(v));
}
__device__ __forceinline__ void fma2(unsigned long long& d, unsigned long long a, unsigned long long b){
    asm("fma.rn.f32x2 %0, %1, %2, %0;" : "+l"(d) : "l"(a), "l"(b));
}

// ---------------------------------------------------------------------------
// Weight transpose (coalesced, smem-tiled):
// OIHW conv_w[n][c*9+r] -> g_wt[(r*1024+c)*512 + n]
// ---------------------------------------------------------------------------
__global__ void __launch_bounds__(256)
transpose_w_kernel(const float* __restrict__ w){
    __shared__ float s[128][73];
    const int tid = threadIdx.x;
    const int n0 = blockIdx.y * 128;
    const int c0 = blockIdx.x * 8;
    const int n  = tid >> 1;
    const int half = tid & 1;
    const float* src = w + (size_t)(n0+n)*KTOT + c0*9 + half*36;
#pragma unroll
    for (int i=0;i<36;i++) s[n][half*36 + i] = src[i];
    __syncthreads();
    const int nn = tid & 127;
    const int u  = tid >> 7;
#pragma unroll
    for (int si=0; si<36; ++si){
        int slot = u*36 + si;
        int cc = slot / 9, r = slot - cc*9;
        g_wt[(size_t)(r*1024 + c0 + cc)*512 + n0 + nn] = s[nn][slot];
    }
}

__global__ void init_kernel(){
    int i = blockIdx.x*256 + threadIdx.x;
    if (i < NB*NBUCKET) g_hist[i] = 0;
    if (i < NB*SEL_CAP) g_sel[i] = 0ULL;
    if (i < NB)         g_cnt[i] = 0;
}

// ---------------------------------------------------------------------------
// 3x3 conv as implicit GEMM, split-K x4 (fp32, packed f32x2 FMA).
// R6's proven inner loop EXACTLY (128x128 tile, 256 thr, 8x8/thread, occ 2);
// each CTA covers a 2304-wide K quarter -> 2048 equal CTAs over 296 slots
// (6.92/slot, makespan 7 quarters = 1.75d vs 2d: -12.5% quantization).
// Raw partials to gmem; deterministic combine adds bias+relu.
// ---------------------------------------------------------------------------
__global__ void __launch_bounds__(256,2)
conv3x3_kernel(const float* __restrict__ X){
    __shared__ __align__(16) float As[2][8][128];
    __shared__ __align__(16) float Bs[2][8][128];
    const int tid = threadIdx.x;
    const int n0 = blockIdx.x * 128;
    const int m0 = blockIdx.y * 128;
    const int kq = blockIdx.z;
    const int KT0 = kq * (KQ/8);       // first ktile of this quarter

    const int a_m = tid & 127;
    const int a_k = (tid >> 7) << 2;   // 0 or 4
    const int am  = m0 + a_m;
    const int bb  = am >> 12;
    const int yx  = am & 4095;
    const int py  = yx >> 6;
    const int px  = yx & 63;
    const float* Xb = X + (size_t)bb * (CIN*NPIX);

    const int w_n = tid & 127;
    const int w_k = (tid >> 7) << 2;

    const int tm = (tid >> 4) << 2;    // 0..60
    const int tn = (tid & 15) << 2;    // 0..60

    unsigned long long acc2[8][4];
#pragma unroll
    for (int i=0;i<8;i++)
#pragma unroll
        for (int jh=0;jh<4;jh++) acc2[i][jh] = 0ULL;

    float ar[4], br[4];
    { // prologue: first ktile of this quarter
        const int kb = KT0 << 3;
        const int r  = kb >> 10;
        const int cb = kb & 1023;
        const int ky = r/3, kx = r - ky*3;
        const int oy = py + ky - 1, ox = px + kx - 1;
        const bool ok = ((unsigned)oy < 64u) && ((unsigned)ox < 64u);
        const float* ap = Xb + ((cb + a_k)*4096 + oy*64 + ox);
#pragma unroll
        for (int i=0;i<4;i++) ar[i] = ok ? ap[i*4096] : 0.f;
        const float* wp = g_wt + (size_t)(kb + w_k)*512 + n0 + w_n;
#pragma unroll
        for (int i=0;i<4;i++) br[i] = wp[i*512];
#pragma unroll
        for (int i=0;i<4;i++) As[0][a_k+i][a_m] = ar[i];
#pragma unroll
        for (int i=0;i<4;i++) Bs[0][w_k+i][w_n] = br[i];
    }
    __syncthreads();

    int buf = 0;
    const int NKT = KQ/8;   // 288
    for (int kt = 0; kt < NKT; ++kt) {
        if (kt + 1 < NKT) {
            const int kb = (KT0 + kt + 1) << 3;
            const int r  = kb >> 10;
            const int cb = kb & 1023;
            const int ky = r/3, kx = r - ky*3;
            const int oy = py + ky - 1, ox = px + kx - 1;
            const bool ok = ((unsigned)oy < 64u) && ((unsigned)ox < 64u);
            const float* ap = Xb + ((cb + a_k)*4096 + oy*64 + ox);
#pragma unroll
            for (int i=0;i<4;i++) ar[i] = ok ? ap[i*4096] : 0.f;
            const float* wp = g_wt + (size_t)(kb + w_k)*512 + n0 + w_n;
#pragma unroll
            for (int i=0;i<4;i++) br[i] = wp[i*512];
        }
#pragma unroll
        for (int kk=0;kk<8;kk++){
            float4 t0 = *(const float4*)&As[buf][kk][tm];
            float4 t1 = *(const float4*)&As[buf][kk][64+tm];
            const unsigned long long* Bp0 = (const unsigned long long*)&Bs[buf][kk][tn];
            const unsigned long long* Bp1 = (const unsigned long long*)&Bs[buf][kk][64+tn];
            unsigned long long bp[4];
            bp[0]=Bp0[0]; bp[1]=Bp0[1]; bp[2]=Bp1[0]; bp[3]=Bp1[1];
            unsigned long long ap2[8];
            ap2[0]=pk2(t0.x,t0.x); ap2[1]=pk2(t0.y,t0.y);
            ap2[2]=pk2(t0.z,t0.z); ap2[3]=pk2(t0.w,t0.w);
            ap2[4]=pk2(t1.x,t1.x); ap2[5]=pk2(t1.y,t1.y);
            ap2[6]=pk2(t1.z,t1.z); ap2[7]=pk2(t1.w,t1.w);
#pragma unroll
            for (int jh=0;jh<4;jh++)
#pragma unroll
                for (int i=0;i<8;i++)
                    fma2(acc2[i][jh], ap2[i], bp[jh]);
        }
        if (kt + 1 < NKT) {
            const int nb2 = buf^1;
#pragma unroll
            for (int i=0;i<4;i++) As[nb2][a_k+i][a_m] = ar[i];
#pragma unroll
            for (int i=0;i<4;i++) Bs[nb2][w_k+i][w_n] = br[i];
        }
        __syncthreads();
        buf ^= 1;
    }

    // epilogue: raw partials (no bias/relu) -> g_part[kq]
    float* gp = g_part + (size_t)kq * MTOT * CMID;
#pragma unroll
    for (int i=0;i<8;i++){
        const int mr = m0 + ((i<4)? (tm+i) : (64+tm+i-4));
        float* op = gp + (size_t)mr*CMID + n0;
#pragma unroll
        for (int jh=0;jh<4;jh++){
            float v0, v1;
            upk2(acc2[i][jh], v0, v1);
            const int j0 = 2*jh, j1 = 2*jh+1;
            const int nc0 = (j0<4)? (tn+j0) : (64+tn+j0-4);
            const int nc1 = (j1<4)? (tn+j1) : (64+tn+j1-4);
            op[nc0] = v0;
            op[nc1] = v1;
        }
    }
}

// ---------------------------------------------------------------------------
// Deterministic split-K combine: ((p0+p1)+p2)+p3 + bias, relu -> g_feat.
// ---------------------------------------------------------------------------
__global__ void __launch_bounds__(256)
combine_kernel(const float* __restrict__ bias){
    const size_t idx = ((size_t)blockIdx.x*256 + threadIdx.x) * 4;  // float4 granular
    const int n = (int)(idx & (CMID-1));
    const float4 p0 = *(const float4*)(g_part + idx);
    const float4 p1 = *(const float4*)(g_part + (size_t)MTOT*CMID + idx);
    const float4 p2 = *(const float4*)(g_part + 2*(size_t)MTOT*CMID + idx);
    const float4 p3 = *(const float4*)(g_part + 3*(size_t)MTOT*CMID + idx);
    const float4 bv = *(const float4*)(bias + n);
    float4 o;
    o.x = fmaxf(((p0.x + p1.x) + p2.x) + p3.x + bv.x, 0.f);
    o.y = fmaxf(((p0.y + p1.y) + p2.y) + p3.y + bv.y, 0.f);
    o.z = fmaxf(((p0.z + p1.z) + p2.z) + p3.z + bv.z, 0.f);
    o.w = fmaxf(((p0.w + p1.w) + p2.w) + p3.w + bv.w, 0.f);
    *(float4*)(g_feat + idx) = o;
}

// ---------------------------------------------------------------------------
// 1x1 heads + softmax + anchor decode + clip + histogram (4 px per warp-iter).
// ---------------------------------------------------------------------------
__global__ void __launch_bounds__(512)
head_kernel(const float* __restrict__ cls_w, const float* __restrict__ cls_b,
            const float* __restrict__ bbox_w, const float* __restrict__ bbox_b,
            const float* __restrict__ im_info){
    extern __shared__ float ws[];
    __shared__ float bs[54];
    __shared__ float obuf[16][4][54];
    const int tid = threadIdx.x;
    for (int i = tid; i < 18*512; i += 512) ws[i] = cls_w[i];
    for (int i = tid; i < 36*512; i += 512) ws[18*512 + i] = bbox_w[i];
    if (tid < 18) bs[tid] = cls_b[tid];
    else if (tid < 54) bs[tid] = bbox_b[tid-18];
    __syncthreads();

    const int lane = tid & 31;
    const int warp = tid >> 5;
    const int gw = blockIdx.x*16 + warp;
    const int nw = gridDim.x*16;
    for (int mb = gw*4; mb < MTOT; mb += nw*4) {
        float fr[4][16];
#pragma unroll
        for (int p=0;p<4;p++){
            const float* f = g_feat + (size_t)(mb+p)*CMID;
#pragma unroll
            for (int j=0;j<16;j++) fr[p][j] = f[lane + 32*j];
        }
        for (int t=0;t<54;t++){
            const float* wr = ws + t*512;
            float s0=0.f, s1=0.f, s2=0.f, s3=0.f;
#pragma unroll
            for (int j=0;j<16;j++){
                float wv = wr[lane+32*j];
                s0 += fr[0][j]*wv; s1 += fr[1][j]*wv;
                s2 += fr[2][j]*wv; s3 += fr[3][j]*wv;
            }
#pragma unroll
            for (int d=16; d>0; d>>=1){
                s0 += __shfl_xor_sync(0xffffffffu, s0, d);
                s1 += __shfl_xor_sync(0xffffffffu, s1, d);
                s2 += __shfl_xor_sync(0xffffffffu, s2, d);
                s3 += __shfl_xor_sync(0xffffffffu, s3, d);
            }
            if (lane==0){
                float bv = bs[t];
                obuf[warp][0][t] = s0 + bv;
                obuf[warp][1][t] = s1 + bv;
                obuf[warp][2][t] = s2 + bv;
                obuf[warp][3][t] = s3 + bv;
            }
        }
        __syncwarp();
#pragma unroll
        for (int p=0;p<4;p++){
            if (lane < 9) {
                const float* o = obuf[warp][p];
                const int m = mb + p;
                const int a  = lane;
                const int b  = m >> 12;
                const int yx = m & 4095;
                const int py = yx >> 6, px = yx & 63;
                float c0 = o[a], c1 = o[9+a];
                float mx = fmaxf(c0,c1);
                float e0 = expf(c0-mx), e1 = expf(c1-mx);
                float sc = e1/(e0+e1);
                float dx = o[18+a*4+0], dy = o[18+a*4+1];
                float dw = o[18+a*4+2], dh = o[18+a*4+3];
                float wa = c_wa[a], ha = c_ha[a];
                float cxa = 7.5f + 16.f*(float)px;
                float cya = 7.5f + 16.f*(float)py;
                float cx = dx*wa + cxa;
                float cy = dy*ha + cya;
                float pw = expf(dw)*wa;
                float ph = expf(dh)*ha;
                float imh = im_info[b*3+0], imw = im_info[b*3+1];
                float x1 = fminf(fmaxf(cx - 0.5f*pw, 0.f), imw - 1.f);
                float y1 = fminf(fmaxf(cy - 0.5f*ph, 0.f), imh - 1.f);
                float x2 = fminf(fmaxf(cx + 0.5f*pw, 0.f), imw - 1.f);
                float y2 = fminf(fmaxf(cy + 0.5f*ph, 0.f), imh - 1.f);
                const int idx = yx*9 + a;
                float* bp = g_boxes + ((size_t)b*NANCH + idx)*4;
                bp[0]=x1; bp[1]=y1; bp[2]=x2; bp[3]=y2;
                unsigned bits = __float_as_uint(sc);
                g_sbits[b*NANCH + idx] = bits;
                atomicAdd(&g_hist[b*NBUCKET + (bits>>16)], 1);
            }
        }
        __syncwarp();
    }
}

// ---------------------------------------------------------------------------
__global__ void __launch_bounds__(1024) thresh_kernel(){
    __shared__ int csum[1024];
    const int b = blockIdx.x;
    const int t = threadIdx.x;
    const int* h = g_hist + b*NBUCKET;
    const int base = t*64;
    int s = 0;
    for (int i=0;i<64;i++) s += h[base+i];
    csum[t] = s;
    __syncthreads();
    for (int d=1; d<1024; d<<=1){
        int add = (t+d < 1024) ? csum[t+d] : 0;
        __syncthreads();
        csum[t] += add;
        __syncthreads();
    }
    int St = csum[t];
    int Sn = (t+1 < 1024) ? csum[t+1] : 0;
    if (St >= PRE_TOPN && Sn < PRE_TOPN){
        int acc = Sn;
        int T = base;
        for (int i=63;i>=0;i--){
            acc += h[base+i];
            if (acc >= PRE_TOPN){ T = base+i; break; }
        }
        g_thr[b] = T;
    }
}

__global__ void compact_kernel(){
    int i = blockIdx.x*256 + threadIdx.x;
    if (i >= NB*NANCH) return;
    int b = i / NANCH;
    int idx = i - b*NANCH;
    unsigned bits = g_sbits[i];
    if ((int)(bits >> 16) >= g_thr[b]){
        int p = atomicAdd(&g_cnt[b], 1);
        if (p < SEL_CAP)
            g_sel[b*SEL_CAP + p] = ((unsigned long long)bits << 32) | (unsigned)(~idx);
    }
}

__global__ void __launch_bounds__(1024) sort_kernel(){
    extern __shared__ unsigned long long sh[];
    const int b = blockIdx.x;
    unsigned long long* gs = g_sel + b*SEL_CAP;
    for (int i=threadIdx.x;i<SEL_CAP;i+=1024) sh[i] = gs[i];
    __syncthreads();
    for (int k=2;k<=SEL_CAP;k<<=1){
        for (int j=k>>1;j>0;j>>=1){
            for (int t=threadIdx.x;t<SEL_CAP/2;t+=1024){
                int i  = 2*t - (t & (j-1));
                int ix = i + j;
                unsigned long long a = sh[i], c = sh[ix];
                bool dir = ((i & k) == 0);
                bool sw  = dir ? (a < c) : (a > c);
                if (sw){ sh[i]=c; sh[ix]=a; }
            }
            __syncthreads();
        }
    }
    for (int i=threadIdx.x;i<SEL_CAP;i+=1024) gs[i]=sh[i];
}

__global__ void __launch_bounds__(1024) nms_kernel(float* __restrict__ out){
    extern __shared__ float sm[];
    float* X1 = sm;
    float* Y1 = X1 + PRE_TOPN;
    float* X2 = Y1 + PRE_TOPN;
    float* Y2 = X2 + PRE_TOPN;
    float* AR = Y2 + PRE_TOPN;
    float* SC = AR + PRE_TOPN;
    __shared__ int   s_pick;
    __shared__ float s_box[5];
    const int b = blockIdx.x;
    const unsigned long long* keys = g_sel + b*SEL_CAP;
    for (int i=threadIdx.x;i<PRE_TOPN;i+=1024){
        unsigned long long kv = keys[i];
        unsigned idx = ~(unsigned)(kv & 0xFFFFFFFFull);
        float sc = __uint_as_float((unsigned)(kv >> 32));
        const float* bp = g_boxes + ((size_t)b*NANCH + idx)*4;
        float x1=bp[0], y1=bp[1], x2=bp[2], y2=bp[3];
        X1[i]=x1; Y1[i]=y1; X2[i]=x2; Y2[i]=y2;
        AR[i]=(x2-x1+1.f)*(y2-y1+1.f);
        SC[i]=sc;
    }
    __syncthreads();
    int p = 0;
    for (int it=0; it<POST_TOPN; ++it){
        if (threadIdx.x == 0){
            while (p < PRE_TOPN && SC[p] == NEGF) p++;
            if (p < PRE_TOPN){
                s_pick = p;
                s_box[0]=X1[p]; s_box[1]=Y1[p]; s_box[2]=X2[p]; s_box[3]=Y2[p]; s_box[4]=AR[p];
                float* r = out + (size_t)(b*POST_TOPN + it)*5;
                r[0]=(float)b; r[1]=X1[p]; r[2]=Y1[p]; r[3]=X2[p]; r[4]=Y2[p];
                out[NB*POST_TOPN*5 + b*POST_TOPN + it] = SC[p];
            } else {
                s_pick = -1;
                float* r = out + (size_t)(b*POST_TOPN + it)*5;
                r[0]=0.f; r[1]=0.f; r[2]=0.f; r[3]=0.f; r[4]=0.f;
                out[NB*POST_TOPN*5 + b*POST_TOPN + it] = 0.f;
            }
        }
        __syncthreads();
        if (s_pick >= 0){
            float bx1=s_box[0], by1=s_box[1], bx2=s_box[2], by2=s_box[3], ba=s_box[4];
            for (int i=threadIdx.x;i<PRE_TOPN;i+=1024){
                float sc = SC[i];
                if (sc == NEGF) continue;
                float xx1 = fmaxf(bx1, X1[i]);
                float yy1 = fmaxf(by1, Y1[i]);
                float xx2 = fminf(bx2, X2[i]);
                float yy2 = fminf(by2, Y2[i]);
                float iw = fmaxf(xx2-xx1+1.f, 0.f);
                float ih = fmaxf(yy2-yy1+1.f, 0.f);
                float inter = iw*ih;
                float iou = inter/(ba + AR[i] - inter);
                if (iou > 0.7f) SC[i] = NEGF;
            }
        }
        __syncthreads();
    }
}

// ---------------------------------------------------------------------------
extern "C" void kernel_launch(void* const* d_in, const int* in_sizes, int n_in,
                              void* d_out, int out_size) {
    (void)in_sizes; (void)n_in; (void)out_size;
    const float* base_feat = (const float*)d_in[0];
    const float* im_info   = (const float*)d_in[1];
    const float* conv_w    = (const float*)d_in[4];
    const float* conv_b    = (const float*)d_in[5];
    const float* cls_w     = (const float*)d_in[6];
    const float* cls_b     = (const float*)d_in[7];
    const float* bbox_w    = (const float*)d_in[8];
    const float* bbox_b    = (const float*)d_in[9];
    float* out = (float*)d_out;

    cudaFuncSetAttribute(head_kernel, cudaFuncAttributeMaxDynamicSharedMemorySize, 54*512*4);
    cudaFuncSetAttribute(sort_kernel, cudaFuncAttributeMaxDynamicSharedMemorySize, SEL_CAP*8);
    cudaFuncSetAttribute(nms_kernel,  cudaFuncAttributeMaxDynamicSharedMemorySize, PRE_TOPN*6*4);

    transpose_w_kernel<<<dim3(128,4), 256>>>(conv_w);
    init_kernel<<<(NB*NBUCKET + 255)/256, 256>>>();
    conv3x3_kernel<<<dim3(4,128,NSPLIT), 256>>>(base_feat);
    combine_kernel<<<(MTOT*CMID/4 + 255)/256, 256>>>(conv_b);
    head_kernel<<<148, 512, 54*512*4>>>(cls_w, cls_b, bbox_w, bbox_b, im_info);
    thresh_kernel<<<NB, 1024>>>();
    compact_kernel<<<(NB*NANCH + 255)/256, 256>>>();
    sort_kernel<<<NB, 1024, SEL_CAP*8>>>();
    nms_kernel<<<NB, 1024, PRE_TOPN*6*4>>>(out);
}

// round 12
// speedup vs baseline: 1.8976x; 1.0144x over previous
#include <cuda_runtime.h>
#include <math.h>

#define NB 4
#define CIN 1024
#define CMID 512
#define NPIX 4096
#define MTOT (NB*NPIX)      /* 16384 */
#define KTOT 9216
#define NSPLIT 4
#define KQ (KTOT/NSPLIT)    /* 2304 */
#define NANCH 36864
#define PRE_TOPN 6000
#define POST_TOPN 300
#define SORT_N 8192
#define NBUCKET 65536
#define NEGF (-1.0e10f)

static __device__ float g_wt[KTOT*CMID];
static __device__ float g_part[(size_t)NSPLIT*MTOT*CMID];   // split-K partials
static __device__ float g_feat[(size_t)MTOT*CMID];
static __device__ float g_boxes[NB*NANCH*4];
static __device__ unsigned g_sbits[NB*NANCH];
static __device__ int g_hist[NB*NBUCKET];
static __device__ int g_thr[NB];
static __device__ int g_cnt[NB];
static __device__ unsigned long long g_sel[NB*SORT_N];

// base anchor widths/heights for (ratio 0.5,1,2) x (scale 8,16,32), centers all at 7.5
__constant__ float c_wa[9] = {184.f,368.f,736.f,128.f,256.f,512.f, 88.f,176.f,352.f};
__constant__ float c_ha[9] = { 96.f,192.f,384.f,128.f,256.f,512.f,176.f,352.f,704.f};

// ---- packed f32x2 helpers (Blackwell) --------------------------------------
__device__ __forceinline__ unsigned long long pk2(float x, float y){
    unsigned long long r;
    asm("mov.b64 %0, {%1,%2};" : "=l"(r) : "f"(x), "f"(y));
    return r;
}
__device__ __forceinline__ void upk2(unsigned long long v, float& x, float& y){
    asm("mov.b64 {%0,%1}, %2;" : "=f"(x), "=f"(y) : "l"(v));
}
__device__ __forceinline__ void fma2(unsigned long long& d, unsigned long long a, unsigned long long b){
    asm("fma.rn.f32x2 %0, %1, %2, %0;" : "+l"(d) : "l"(a), "l"(b));
}

// ---------------------------------------------------------------------------
// Weight transpose (coalesced, smem-tiled):
// OIHW conv_w[n][c*9+r] -> g_wt[(r*1024+c)*512 + n]
// ---------------------------------------------------------------------------
__global__ void __launch_bounds__(256)
transpose_w_kernel(const float* __restrict__ w){
    __shared__ float s[128][73];
    const int tid = threadIdx.x;
    const int n0 = blockIdx.y * 128;
    const int c0 = blockIdx.x * 8;
    const int n  = tid >> 1;
    const int half = tid & 1;
    const float* src = w + (size_t)(n0+n)*KTOT + c0*9 + half*36;
#pragma unroll
    for (int i=0;i<36;i++) s[n][half*36 + i] = src[i];
    __syncthreads();
    const int nn = tid & 127;
    const int u  = tid >> 7;
#pragma unroll
    for (int si=0; si<36; ++si){
        int slot = u*36 + si;
        int cc = slot / 9, r = slot - cc*9;
        g_wt[(size_t)(r*1024 + c0 + cc)*512 + n0 + nn] = s[nn][slot];
    }
}

__global__ void init_kernel(){
    int i = blockIdx.x*256 + threadIdx.x;
    if (i < NB*NBUCKET) g_hist[i] = 0;
    if (i < NB*SORT_N)  g_sel[i] = 0ULL;
    if (i < NB)         g_cnt[i] = 0;
}

// ---------------------------------------------------------------------------
// 3x3 conv as implicit GEMM, split-K x4 (fp32, packed f32x2 FMA).
// R6's proven inner loop (128x128 tile, 256 thr, 8x8/thread, occ 2); each CTA
// covers a 2304-wide K quarter -> 2048 CTAs / 296 slots (makespan 7 quarters,
// 1.2% quantization). Raw partials -> gmem; deterministic combine.
// ---------------------------------------------------------------------------
__global__ void __launch_bounds__(256,2)
conv3x3_kernel(const float* __restrict__ X){
    __shared__ __align__(16) float As[2][8][128];
    __shared__ __align__(16) float Bs[2][8][128];
    const int tid = threadIdx.x;
    const int n0 = blockIdx.x * 128;
    const int m0 = blockIdx.y * 128;
    const int kq = blockIdx.z;
    const int KT0 = kq * (KQ/8);

    const int a_m = tid & 127;
    const int a_k = (tid >> 7) << 2;
    const int am  = m0 + a_m;
    const int bb  = am >> 12;
    const int yx  = am & 4095;
    const int py  = yx >> 6;
    const int px  = yx & 63;
    const float* Xb = X + (size_t)bb * (CIN*NPIX);

    const int w_n = tid & 127;
    const int w_k = (tid >> 7) << 2;

    const int tm = (tid >> 4) << 2;
    const int tn = (tid & 15) << 2;

    unsigned long long acc2[8][4];
#pragma unroll
    for (int i=0;i<8;i++)
#pragma unroll
        for (int jh=0;jh<4;jh++) acc2[i][jh] = 0ULL;

    float ar[4], br[4];
    {
        const int kb = KT0 << 3;
        const int r  = kb >> 10;
        const int cb = kb & 1023;
        const int ky = r/3, kx = r - ky*3;
        const int oy = py + ky - 1, ox = px + kx - 1;
        const bool ok = ((unsigned)oy < 64u) && ((unsigned)ox < 64u);
        const float* ap = Xb + ((cb + a_k)*4096 + oy*64 + ox);
#pragma unroll
        for (int i=0;i<4;i++) ar[i] = ok ? ap[i*4096] : 0.f;
        const float* wp = g_wt + (size_t)(kb + w_k)*512 + n0 + w_n;
#pragma unroll
        for (int i=0;i<4;i++) br[i] = wp[i*512];
#pragma unroll
        for (int i=0;i<4;i++) As[0][a_k+i][a_m] = ar[i];
#pragma unroll
        for (int i=0;i<4;i++) Bs[0][w_k+i][w_n] = br[i];
    }
    __syncthreads();

    int buf = 0;
    const int NKT = KQ/8;   // 288
    for (int kt = 0; kt < NKT; ++kt) {
        if (kt + 1 < NKT) {
            const int kb = (KT0 + kt + 1) << 3;
            const int r  = kb >> 10;
            const int cb = kb & 1023;
            const int ky = r/3, kx = r - ky*3;
            const int oy = py + ky - 1, ox = px + kx - 1;
            const bool ok = ((unsigned)oy < 64u) && ((unsigned)ox < 64u);
            const float* ap = Xb + ((cb + a_k)*4096 + oy*64 + ox);
#pragma unroll
            for (int i=0;i<4;i++) ar[i] = ok ? ap[i*4096] : 0.f;
            const float* wp = g_wt + (size_t)(kb + w_k)*512 + n0 + w_n;
#pragma unroll
            for (int i=0;i<4;i++) br[i] = wp[i*512];
        }
#pragma unroll
        for (int kk=0;kk<8;kk++){
            float4 t0 = *(const float4*)&As[buf][kk][tm];
            float4 t1 = *(const float4*)&As[buf][kk][64+tm];
            const unsigned long long* Bp0 = (const unsigned long long*)&Bs[buf][kk][tn];
            const unsigned long long* Bp1 = (const unsigned long long*)&Bs[buf][kk][64+tn];
            unsigned long long bp[4];
            bp[0]=Bp0[0]; bp[1]=Bp0[1]; bp[2]=Bp1[0]; bp[3]=Bp1[1];
            unsigned long long ap2[8];
            ap2[0]=pk2(t0.x,t0.x); ap2[1]=pk2(t0.y,t0.y);
            ap2[2]=pk2(t0.z,t0.z); ap2[3]=pk2(t0.w,t0.w);
            ap2[4]=pk2(t1.x,t1.x); ap2[5]=pk2(t1.y,t1.y);
            ap2[6]=pk2(t1.z,t1.z); ap2[7]=pk2(t1.w,t1.w);
#pragma unroll
            for (int jh=0;jh<4;jh++)
#pragma unroll
                for (int i=0;i<8;i++)
                    fma2(acc2[i][jh], ap2[i], bp[jh]);
        }
        if (kt + 1 < NKT) {
            const int nb2 = buf^1;
#pragma unroll
            for (int i=0;i<4;i++) As[nb2][a_k+i][a_m] = ar[i];
#pragma unroll
            for (int i=0;i<4;i++) Bs[nb2][w_k+i][w_n] = br[i];
        }
        __syncthreads();
        buf ^= 1;
    }

    float* gp = g_part + (size_t)kq * MTOT * CMID;
#pragma unroll
    for (int i=0;i<8;i++){
        const int mr = m0 + ((i<4)? (tm+i) : (64+tm+i-4));
        float* op = gp + (size_t)mr*CMID + n0;
#pragma unroll
        for (int jh=0;jh<4;jh++){
            float v0, v1;
            upk2(acc2[i][jh], v0, v1);
            const int j0 = 2*jh, j1 = 2*jh+1;
            const int nc0 = (j0<4)? (tn+j0) : (64+tn+j0-4);
            const int nc1 = (j1<4)? (tn+j1) : (64+tn+j1-4);
            op[nc0] = v0;
            op[nc1] = v1;
        }
    }
}

// ---------------------------------------------------------------------------
// Deterministic split-K combine: ((p0+p1)+p2)+p3 + bias, relu -> g_feat.
// ---------------------------------------------------------------------------
__global__ void __launch_bounds__(256)
combine_kernel(const float* __restrict__ bias){
    const size_t idx = ((size_t)blockIdx.x*256 + threadIdx.x) * 4;
    const int n = (int)(idx & (CMID-1));
    const float4 p0 = *(const float4*)(g_part + idx);
    const float4 p1 = *(const float4*)(g_part + (size_t)MTOT*CMID + idx);
    const float4 p2 = *(const float4*)(g_part + 2*(size_t)MTOT*CMID + idx);
    const float4 p3 = *(const float4*)(g_part + 3*(size_t)MTOT*CMID + idx);
    const float4 bv = *(const float4*)(bias + n);
    float4 o;
    o.x = fmaxf(((p0.x + p1.x) + p2.x) + p3.x + bv.x, 0.f);
    o.y = fmaxf(((p0.y + p1.y) + p2.y) + p3.y + bv.y, 0.f);
    o.z = fmaxf(((p0.z + p1.z) + p2.z) + p3.z + bv.z, 0.f);
    o.w = fmaxf(((p0.w + p1.w) + p2.w) + p3.w + bv.w, 0.f);
    *(float4*)(g_feat + idx) = o;
}

// ---------------------------------------------------------------------------
// 1x1 heads + softmax + anchor decode + clip + histogram (4 px per warp-iter).
// ---------------------------------------------------------------------------
__global__ void __launch_bounds__(512)
head_kernel(const float* __restrict__ cls_w, const float* __restrict__ cls_b,
            const float* __restrict__ bbox_w, const float* __restrict__ bbox_b,
            const float* __restrict__ im_info){
    extern __shared__ float ws[];
    __shared__ float bs[54];
    __shared__ float obuf[16][4][54];
    const int tid = threadIdx.x;
    for (int i = tid; i < 18*512; i += 512) ws[i] = cls_w[i];
    for (int i = tid; i < 36*512; i += 512) ws[18*512 + i] = bbox_w[i];
    if (tid < 18) bs[tid] = cls_b[tid];
    else if (tid < 54) bs[tid] = bbox_b[tid-18];
    __syncthreads();

    const int lane = tid & 31;
    const int warp = tid >> 5;
    const int gw = blockIdx.x*16 + warp;
    const int nw = gridDim.x*16;
    for (int mb = gw*4; mb < MTOT; mb += nw*4) {
        float fr[4][16];
#pragma unroll
        for (int p=0;p<4;p++){
            const float* f = g_feat + (size_t)(mb+p)*CMID;
#pragma unroll
            for (int j=0;j<16;j++) fr[p][j] = f[lane + 32*j];
        }
        for (int t=0;t<54;t++){
            const float* wr = ws + t*512;
            float s0=0.f, s1=0.f, s2=0.f, s3=0.f;
#pragma unroll
            for (int j=0;j<16;j++){
                float wv = wr[lane+32*j];
                s0 += fr[0][j]*wv; s1 += fr[1][j]*wv;
                s2 += fr[2][j]*wv; s3 += fr[3][j]*wv;
            }
#pragma unroll
            for (int d=16; d>0; d>>=1){
                s0 += __shfl_xor_sync(0xffffffffu, s0, d);
                s1 += __shfl_xor_sync(0xffffffffu, s1, d);
                s2 += __shfl_xor_sync(0xffffffffu, s2, d);
                s3 += __shfl_xor_sync(0xffffffffu, s3, d);
            }
            if (lane==0){
                float bv = bs[t];
                obuf[warp][0][t] = s0 + bv;
                obuf[warp][1][t] = s1 + bv;
                obuf[warp][2][t] = s2 + bv;
                obuf[warp][3][t] = s3 + bv;
            }
        }
        __syncwarp();
#pragma unroll
        for (int p=0;p<4;p++){
            if (lane < 9) {
                const float* o = obuf[warp][p];
                const int m = mb + p;
                const int a  = lane;
                const int b  = m >> 12;
                const int yx = m & 4095;
                const int py = yx >> 6, px = yx & 63;
                float c0 = o[a], c1 = o[9+a];
                float mx = fmaxf(c0,c1);
                float e0 = expf(c0-mx), e1 = expf(c1-mx);
                float sc = e1/(e0+e1);
                float dx = o[18+a*4+0], dy = o[18+a*4+1];
                float dw = o[18+a*4+2], dh = o[18+a*4+3];
                float wa = c_wa[a], ha = c_ha[a];
                float cxa = 7.5f + 16.f*(float)px;
                float cya = 7.5f + 16.f*(float)py;
                float cx = dx*wa + cxa;
                float cy = dy*ha + cya;
                float pw = expf(dw)*wa;
                float ph = expf(dh)*ha;
                float imh = im_info[b*3+0], imw = im_info[b*3+1];
                float x1 = fminf(fmaxf(cx - 0.5f*pw, 0.f), imw - 1.f);
                float y1 = fminf(fmaxf(cy - 0.5f*ph, 0.f), imh - 1.f);
                float x2 = fminf(fmaxf(cx + 0.5f*pw, 0.f), imw - 1.f);
                float y2 = fminf(fmaxf(cy + 0.5f*ph, 0.f), imh - 1.f);
                const int idx = yx*9 + a;
                float* bp = g_boxes + ((size_t)b*NANCH + idx)*4;
                bp[0]=x1; bp[1]=y1; bp[2]=x2; bp[3]=y2;
                unsigned bits = __float_as_uint(sc);
                g_sbits[b*NANCH + idx] = bits;
                atomicAdd(&g_hist[b*NBUCKET + (bits>>16)], 1);
            }
        }
        __syncwarp();
    }
}

// ---------------------------------------------------------------------------
__global__ void __launch_bounds__(1024) thresh_kernel(){
    __shared__ int csum[1024];
    const int b = blockIdx.x;
    const int t = threadIdx.x;
    const int* h = g_hist + b*NBUCKET;
    const int base = t*64;
    int s = 0;
    for (int i=0;i<64;i++) s += h[base+i];
    csum[t] = s;
    __syncthreads();
    for (int d=1; d<1024; d<<=1){
        int add = (t+d < 1024) ? csum[t+d] : 0;
        __syncthreads();
        csum[t] += add;
        __syncthreads();
    }
    int St = csum[t];
    int Sn = (t+1 < 1024) ? csum[t+1] : 0;
    if (St >= PRE_TOPN && Sn < PRE_TOPN){
        int acc = Sn;
        int T = base;
        for (int i=63;i>=0;i--){
            acc += h[base+i];
            if (acc >= PRE_TOPN){ T = base+i; break; }
        }
        g_thr[b] = T;
    }
}

__global__ void compact_kernel(){
    int i = blockIdx.x*256 + threadIdx.x;
    if (i >= NB*NANCH) return;
    int b = i / NANCH;
    int idx = i - b*NANCH;
    unsigned bits = g_sbits[i];
    if ((int)(bits >> 16) >= g_thr[b]){
        int p = atomicAdd(&g_cnt[b], 1);
        if (p < SORT_N)
            g_sel[b*SORT_N + p] = ((unsigned long long)bits << 32) | (unsigned)(~idx);
    }
}

// ---------------------------------------------------------------------------
// In-smem bitonic sort of 8192 packed keys per image (descending).
// Threshold construction bounds selected count to < 6000 + bucket(T) << 8192.
// ---------------------------------------------------------------------------
__global__ void __launch_bounds__(1024) sort_kernel(){
    extern __shared__ unsigned long long sh[];
    const int b = blockIdx.x;
    unsigned long long* gs = g_sel + b*SORT_N;
    for (int i=threadIdx.x;i<SORT_N;i+=1024) sh[i] = gs[i];
    __syncthreads();
    for (int k=2;k<=SORT_N;k<<=1){
        for (int j=k>>1;j>0;j>>=1){
            for (int t=threadIdx.x;t<SORT_N/2;t+=1024){
                int i  = 2*t - (t & (j-1));
                int ix = i + j;
                unsigned long long a = sh[i], c = sh[ix];
                bool dir = ((i & k) == 0);
                bool sw  = dir ? (a < c) : (a > c);
                if (sw){ sh[i]=c; sh[ix]=a; }
            }
            __syncthreads();
        }
    }
    for (int i=threadIdx.x;i<SORT_N;i+=1024) gs[i]=sh[i];
}

// ---------------------------------------------------------------------------
// Greedy NMS on sorted top-6000; pick step uses warp-0 ballot scan.
// ---------------------------------------------------------------------------
__global__ void __launch_bounds__(1024) nms_kernel(float* __restrict__ out){
    extern __shared__ float sm[];
    float* X1 = sm;
    float* Y1 = X1 + PRE_TOPN;
    float* X2 = Y1 + PRE_TOPN;
    float* Y2 = X2 + PRE_TOPN;
    float* AR = Y2 + PRE_TOPN;
    float* SC = AR + PRE_TOPN;
    __shared__ int   s_pick;
    __shared__ float s_box[5];
    const int b = blockIdx.x;
    const unsigned long long* keys = g_sel + b*SORT_N;
    for (int i=threadIdx.x;i<PRE_TOPN;i+=1024){
        unsigned long long kv = keys[i];
        unsigned idx = ~(unsigned)(kv & 0xFFFFFFFFull);
        float sc = __uint_as_float((unsigned)(kv >> 32));
        const float* bp = g_boxes + ((size_t)b*NANCH + idx)*4;
        float x1=bp[0], y1=bp[1], x2=bp[2], y2=bp[3];
        X1[i]=x1; Y1[i]=y1; X2[i]=x2; Y2[i]=y2;
        AR[i]=(x2-x1+1.f)*(y2-y1+1.f);
        SC[i]=sc;
    }
    __syncthreads();
    const int lane = threadIdx.x & 31;
    int p = 0;   // warp-0 shared scan cursor (uniform within warp)
    for (int it=0; it<POST_TOPN; ++it){
        if (threadIdx.x < 32){
            // warp-ballot first-live scan from p
            int found = -1;
            while (found < 0 && p < PRE_TOPN){
                int ii = p + lane;
                bool live = (ii < PRE_TOPN) && (SC[ii] != NEGF);
                unsigned m = __ballot_sync(0xffffffffu, live);
                if (m) found = p + __ffs(m) - 1;
                else   p += 32;
            }
            if (threadIdx.x == 0){
                if (found >= 0){
                    s_pick = found;
                    s_box[0]=X1[found]; s_box[1]=Y1[found];
                    s_box[2]=X2[found]; s_box[3]=Y2[found]; s_box[4]=AR[found];
                    float* r = out + (size_t)(b*POST_TOPN + it)*5;
                    r[0]=(float)b; r[1]=X1[found]; r[2]=Y1[found]; r[3]=X2[found]; r[4]=Y2[found];
                    out[NB*POST_TOPN*5 + b*POST_TOPN + it] = SC[found];
                } else {
                    s_pick = -1;
                    float* r = out + (size_t)(b*POST_TOPN + it)*5;
                    r[0]=0.f; r[1]=0.f; r[2]=0.f; r[3]=0.f; r[4]=0.f;
                    out[NB*POST_TOPN*5 + b*POST_TOPN + it] = 0.f;
                }
            }
            if (found >= 0) p = found;   // next scan resumes at the pick (it gets suppressed)
        }
        __syncthreads();
        if (s_pick >= 0){
            float bx1=s_box[0], by1=s_box[1], bx2=s_box[2], by2=s_box[3], ba=s_box[4];
            for (int i=threadIdx.x;i<PRE_TOPN;i+=1024){
                float sc = SC[i];
                if (sc == NEGF) continue;
                float xx1 = fmaxf(bx1, X1[i]);
                float yy1 = fmaxf(by1, Y1[i]);
                float xx2 = fminf(bx2, X2[i]);
                float yy2 = fminf(by2, Y2[i]);
                float iw = fmaxf(xx2-xx1+1.f, 0.f);
                float ih = fmaxf(yy2-yy1+1.f, 0.f);
                float inter = iw*ih;
                float iou = inter/(ba + AR[i] - inter);
                if (iou > 0.7f) SC[i] = NEGF;   // suppresses the pick too (iou=1)
            }
        }
        __syncthreads();
    }
}

// ---------------------------------------------------------------------------
extern "C" void kernel_launch(void* const* d_in, const int* in_sizes, int n_in,
                              void* d_out, int out_size) {
    (void)in_sizes; (void)n_in; (void)out_size;
    const float* base_feat = (const float*)d_in[0];
    const float* im_info   = (const float*)d_in[1];
    const float* conv_w    = (const float*)d_in[4];
    const float* conv_b    = (const float*)d_in[5];
    const float* cls_w     = (const float*)d_in[6];
    const float* cls_b     = (const float*)d_in[7];
    const float* bbox_w    = (const float*)d_in[8];
    const float* bbox_b    = (const float*)d_in[9];
    float* out = (float*)d_out;

    cudaFuncSetAttribute(head_kernel, cudaFuncAttributeMaxDynamicSharedMemorySize, 54*512*4);
    cudaFuncSetAttribute(sort_kernel, cudaFuncAttributeMaxDynamicSharedMemorySize, SORT_N*8);
    cudaFuncSetAttribute(nms_kernel,  cudaFuncAttributeMaxDynamicSharedMemorySize, PRE_TOPN*6*4);

    transpose_w_kernel<<<dim3(128,4), 256>>>(conv_w);
    init_kernel<<<(NB*NBUCKET + 255)/256, 256>>>();
    conv3x3_kernel<<<dim3(4,128,NSPLIT), 256>>>(base_feat);
    combine_kernel<<<(MTOT*CMID/4 + 255)/256, 256>>>(conv_b);
    head_kernel<<<148, 512, 54*512*4>>>(cls_w, cls_b, bbox_w, bbox_b, im_info);
    thresh_kernel<<<NB, 1024>>>();
    compact_kernel<<<(NB*NANCH + 255)/256, 256>>>();
    sort_kernel<<<NB, 1024, SORT_N*8>>>();
    nms_kernel<<<NB, 1024, PRE_TOPN*6*4>>>(out);
}